// round 15
// baseline (speedup 1.0000x reference)
#include <cuda_runtime.h>
#include <cstdint>

#define DIMS 128
#define NLAB 5
#define MAXN 50000
#define MAXE 600000
#define GTHREADS 512

// ---------------- device scratch ----------------
__device__ float g_W2[2][DIMS * DIMS];
__device__ float g_Wt[3][DIMS * 144];
__device__ float g_c[2][NLAB];
__device__ float g_gate[2][MAXN];
__device__ float g_hin[MAXN * DIMS];
__device__ float g_hout[MAXN * DIMS];
__device__ float g_acc[MAXN * DIMS];          // xl (from GEMM)
__device__ int   g_cnt[2][MAXN];              // per-node degree (0: in-list over dst, 1: out-list over src)
__device__ int   g_off[2][MAXN];              // CSR offsets
__device__ int   g_pos[2][MAXN];              // fill cursors
__device__ unsigned g_list[2][MAXE];          // packed: node | (label<<20)

__device__ __forceinline__ float sigmoidf_(float x) {
    return 1.0f / (1.0f + __expf(-x));
}

__device__ __forceinline__ float tf32r(float x) {
    uint32_t u;
    asm("cvt.rna.tf32.f32 %0, %1;" : "=r"(u) : "f"(x));
    return __uint_as_float(u);
}

__device__ __forceinline__ void mma_tf32(float* c, uint32_t a0, uint32_t a1,
                                         uint32_t a2, uint32_t a3,
                                         uint32_t b0, uint32_t b1) {
    asm volatile(
        "mma.sync.aligned.m16n8k8.row.col.f32.tf32.tf32.f32 "
        "{%0,%1,%2,%3}, {%4,%5,%6,%7}, {%8,%9}, {%0,%1,%2,%3};"
        : "+f"(c[0]), "+f"(c[1]), "+f"(c[2]), "+f"(c[3])
        : "r"(a0), "r"(a1), "r"(a2), "r"(a3), "r"(b0), "r"(b1));
}

// ---------------- prep: W2 = W @ W ----------------
__global__ void prep_w2_kernel(const float* __restrict__ Win,
                               const float* __restrict__ Wout) {
    __shared__ float wrow[DIMS];
    const float* W = (blockIdx.y == 0) ? Win : Wout;
    int r = blockIdx.x, c = threadIdx.x;
    wrow[c] = W[r * DIMS + c];
    __syncthreads();
    float s = 0.0f;
#pragma unroll 8
    for (int k = 0; k < DIMS; k++) s += wrow[k] * W[k * DIMS + c];
    g_W2[blockIdx.y][r * DIMS + c] = s;
}

// ---------------- prep: gate constants ----------------
__global__ void prep_c_kernel(const float* __restrict__ Wg_in,
                              const float* __restrict__ blab_in,
                              const float* __restrict__ bg_in,
                              const float* __restrict__ Wg_out,
                              const float* __restrict__ blab_out,
                              const float* __restrict__ bg_out) {
    int t = threadIdx.x;
    if (t >= 2 * NLAB) return;
    int w = t / NLAB, l = t % NLAB;
    const float* Wg = w ? Wg_out : Wg_in;
    const float* bl = w ? blab_out : blab_in;
    const float* bg = w ? bg_out : bg_in;
    float s = bg[l];
    for (int d = 0; d < DIMS; d++) s += bl[l * DIMS + d] * Wg[d];
    g_c[w][l] = s;
}

// ---------------- prep: quad-layout tf32 W images ----------------
__global__ void prep_wt_kernel(const float* __restrict__ Wloop) {
    int w = blockIdx.x;
    const float* W = (w == 0) ? Wloop : g_W2[w - 1];
    for (int idx = threadIdx.x; idx < DIMS * DIMS; idx += blockDim.x) {
        int k = idx >> 7, n = idx & 127;
        float v = W[idx];
        int ks = k >> 3, kk = k & 7;
        int pos = (ks >> 1) * 16 + (kk & 3) * 4 + (ks & 1) * 2 + (kk >> 2);
        g_Wt[w][n * 144 + pos] = tf32r(v);
    }
}

// ---------------- CSR build ----------------
__global__ void zero_cnt_kernel(int N) {
    int i = blockIdx.x * blockDim.x + threadIdx.x;
    if (i < N) { g_cnt[0][i] = 0; g_cnt[1][i] = 0; }
}

__global__ void hist_kernel(const int* __restrict__ src,
                            const int* __restrict__ dst, int E, int N) {
    int e = blockIdx.x * blockDim.x + threadIdx.x;
    if (e >= E) return;
    int s = min(max(src[e], 0), N - 1);
    int d = min(max(dst[e], 0), N - 1);
    atomicAdd(&g_cnt[0][d], 1);
    atomicAdd(&g_cnt[1][s], 1);
}

// single-CTA two-level exclusive scan over both count arrays
__global__ __launch_bounds__(1024) void scan_kernel(int N) {
    __shared__ int tmp[1024];
    int tid = threadIdx.x;
    int chunk = (N + 1023) / 1024;
    for (int dir = 0; dir < 2; dir++) {
        const int* cnt = g_cnt[dir];
        int* off = g_off[dir];
        int* pos = g_pos[dir];
        int base = tid * chunk;
        int s = 0;
        for (int i = 0; i < chunk; i++) {
            int idx = base + i;
            if (idx < N) s += cnt[idx];
        }
        tmp[tid] = s;
        __syncthreads();
        // Hillis-Steele inclusive scan
        for (int o = 1; o < 1024; o <<= 1) {
            int v = (tid >= o) ? tmp[tid - o] : 0;
            __syncthreads();
            tmp[tid] += v;
            __syncthreads();
        }
        int run = tmp[tid] - s;   // exclusive prefix of this chunk
        for (int i = 0; i < chunk; i++) {
            int idx = base + i;
            if (idx < N) {
                off[idx] = run;
                pos[idx] = run;
                run += cnt[idx];
            }
        }
        __syncthreads();
    }
}

__global__ void fill_kernel(const int* __restrict__ src,
                            const int* __restrict__ dst,
                            const int* __restrict__ lab, int E, int N) {
    int e = blockIdx.x * blockDim.x + threadIdx.x;
    if (e >= E) return;
    int s = min(max(src[e], 0), N - 1);
    int d = min(max(dst[e], 0), N - 1);
    int l = min(max(lab[e], 0), NLAB - 1);
    int i0 = atomicAdd(&g_pos[0][d], 1);
    g_list[0][i0] = (unsigned)s | ((unsigned)l << 20);
    int i1 = atomicAdd(&g_pos[1][s], 1);
    g_list[1][i1] = (unsigned)d | ((unsigned)l << 20);
}

// ---------------- mma.sync tf32 GEMM (unchanged from R14) ----------------
#define AS_STRIDE 132
#define WH_STRIDE 144
#define SMEM_AS 0
#define SMEM_WH (128 * AS_STRIDE)
#define ST_STRIDE 132
#define GEMM_SMEM ((128 * AS_STRIDE + 128 * WH_STRIDE) * 4)

__global__ __launch_bounds__(GTHREADS) void gemm_mma_kernel(const float* __restrict__ x,
                                                            const float* __restrict__ b_loop,
                                                            const float* __restrict__ Wg_loop,
                                                            const float* __restrict__ bg_loop,
                                                            const float* __restrict__ Wg_in,
                                                            const float* __restrict__ Wg_out,
                                                            int M) {
    extern __shared__ float smem[];
    float* As = smem + SMEM_AS;
    float* Wh = smem + SMEM_WH;
    __shared__ float sg[DIMS * 2];

    int tid = threadIdx.x;
    int wid = tid >> 5, lane = tid & 31;
    int g = lane >> 2, t4 = lane & 3;
    int rg = wid & 7;
    int ch = wid >> 3;
    int m0 = blockIdx.x * 128;
    int m0w = rg * 16;

    const float4* x4 = (const float4*)x;
#pragma unroll
    for (int i = 0; i < 8; i++) {
        int fidx = tid + i * GTHREADS;
        int r = fidx >> 5, kq = fidx & 31;
        float4 v = make_float4(0.f, 0.f, 0.f, 0.f);
        if (m0 + r < M) v = x4[(size_t)(m0 + r) * 32 + kq];
        v.x = tf32r(v.x); v.y = tf32r(v.y); v.z = tf32r(v.z); v.w = tf32r(v.w);
        *(float4*)&As[r * AS_STRIDE + kq * 4] = v;
    }
    __syncthreads();

    int rloc0 = m0w + g, rloc1 = rloc0 + 8;
    const float* pa0 = As + rloc0 * AS_STRIDE;
    const float* pa1 = As + rloc1 * AS_STRIDE;
    uint32_t af[16][4];
#pragma unroll
    for (int ks = 0; ks < 16; ks++) {
        int k0 = ks * 8;
        af[ks][0] = __float_as_uint(pa0[k0 + t4]);
        af[ks][1] = __float_as_uint(pa1[k0 + t4]);
        af[ks][2] = __float_as_uint(pa0[k0 + t4 + 4]);
        af[ks][3] = __float_as_uint(pa1[k0 + t4 + 4]);
    }

    for (int w = 0; w < 3; w++) {
        __syncthreads();
        {
            const float4* srcp = (const float4*)g_Wt[w];
            float4* dstp = (float4*)Wh;
#pragma unroll
            for (int i = 0; i < 9; i++) {
                int fi = tid + i * GTHREADS;
                if (fi < 128 * WH_STRIDE / 4) dstp[fi] = srcp[fi];
            }
        }
        __syncthreads();

        float acc[8][4];
#pragma unroll
        for (int j = 0; j < 8; j++)
#pragma unroll
            for (int q = 0; q < 4; q++) acc[j][q] = 0.0f;

#pragma unroll
        for (int ks2 = 0; ks2 < 8; ks2++) {
            int ke = ks2 * 2, ko = ke + 1;
#pragma unroll
            for (int j = 0; j < 8; j++) {
                int n = (ch * 8 + j) * 8 + g;
                float4 bq = *(const float4*)&Wh[n * WH_STRIDE + ks2 * 16 + t4 * 4];
                mma_tf32(acc[j], af[ke][0], af[ke][1], af[ke][2], af[ke][3],
                         __float_as_uint(bq.x), __float_as_uint(bq.y));
                mma_tf32(acc[j], af[ko][0], af[ko][1], af[ko][2], af[ko][3],
                         __float_as_uint(bq.z), __float_as_uint(bq.w));
            }
        }

        float p0 = 0.f, p1 = 0.f;
        if (w == 0) {
#pragma unroll
            for (int j = 0; j < 8; j++) {
                int c0 = ch * 64 + j * 8 + t4 * 2;
                float2 bl2 = *(const float2*)&b_loop[c0];
                float2 wg2 = *(const float2*)&Wg_loop[c0];
                acc[j][0] += bl2.x; acc[j][1] += bl2.y;
                acc[j][2] += bl2.x; acc[j][3] += bl2.y;
                p0 += acc[j][0] * wg2.x + acc[j][1] * wg2.y;
                p1 += acc[j][2] * wg2.x + acc[j][3] * wg2.y;
            }
        } else {
            const float* Wg = (w == 2) ? Wg_out : Wg_in;
#pragma unroll
            for (int j = 0; j < 8; j++) {
                int c0 = ch * 64 + j * 8 + t4 * 2;
                float2 wg2 = *(const float2*)&Wg[c0];
                p0 += acc[j][0] * wg2.x + acc[j][1] * wg2.y;
                p1 += acc[j][2] * wg2.x + acc[j][3] * wg2.y;
            }
        }
        p0 += __shfl_xor_sync(0xffffffffu, p0, 1);
        p0 += __shfl_xor_sync(0xffffffffu, p0, 2);
        p1 += __shfl_xor_sync(0xffffffffu, p1, 1);
        p1 += __shfl_xor_sync(0xffffffffu, p1, 2);
        if (t4 == 0) {
            sg[rloc0 * 2 + ch] = p0;
            sg[rloc1 * 2 + ch] = p1;
        }
        __syncthreads();

        if (w == 0) {
            float bgv = __ldg(&bg_loop[0]);
            float g0 = sigmoidf_(sg[rloc0 * 2] + sg[rloc0 * 2 + 1] + bgv);
            float g1 = sigmoidf_(sg[rloc1 * 2] + sg[rloc1 * 2 + 1] + bgv);
#pragma unroll
            for (int j = 0; j < 8; j++) {
                acc[j][0] *= g0; acc[j][1] *= g0;
                acc[j][2] *= g1; acc[j][3] *= g1;
            }
        } else {
            int dir = w - 1;
            if (tid < DIMS) {
                int row = m0 + tid;
                if (row < M) g_gate[dir][row] = sg[tid * 2] + sg[tid * 2 + 1];
            }
        }

        float* stage = Wh;
#pragma unroll
        for (int j = 0; j < 8; j++) {
            int c0 = ch * 64 + j * 8 + t4 * 2;
            *(float2*)&stage[rloc0 * ST_STRIDE + c0] = make_float2(acc[j][0], acc[j][1]);
            *(float2*)&stage[rloc1 * ST_STRIDE + c0] = make_float2(acc[j][2], acc[j][3]);
        }
        __syncthreads();

        float* outp = (w == 0) ? g_acc : ((w == 1) ? g_hin : g_hout);
#pragma unroll
        for (int i = 0; i < 8; i++) {
            int fidx = tid + i * GTHREADS;
            int r = fidx >> 5, cq = fidx & 31;
            int row = m0 + r;
            if (row < M)
                *(float4*)&outp[(size_t)row * 128 + cq * 4] = *(float4*)&stage[r * ST_STRIDE + cq * 4];
        }
    }
}

// ---------------- gather: warp per node, no atomics, fused xl + relu + store ----------------
__global__ void gather_kernel(const float* __restrict__ blab_in,
                              const float* __restrict__ blab_out,
                              float* __restrict__ out, int N) {
    int v = (int)((blockIdx.x * (unsigned)blockDim.x + threadIdx.x) >> 5);
    int lane = threadIdx.x & 31;
    if (v >= N) return;

    float4 acc = ((const float4*)g_acc)[(size_t)v * 32 + lane];

#pragma unroll
    for (int dir = 0; dir < 2; dir++) {
        const float* h = dir ? g_hout : g_hin;
        const float* bl = dir ? blab_out : blab_in;
        int deg = g_cnt[dir][v];
        int off = g_off[dir][v];
        const unsigned* lst = g_list[dir] + off;

        unsigned e = (deg > 0) ? lst[0] : 0u;
        for (int i = 0; i < deg; i++) {
            unsigned en = (i + 1 < deg) ? lst[i + 1] : 0u;   // prefetch next entry
            int u = (int)(e & 0xFFFFFu);
            int l = (int)(e >> 20);
            float gate = sigmoidf_(g_gate[dir][u] + g_c[dir][l]);
            float4 m = ((const float4*)h)[(size_t)u * 32 + lane];
            float4 b = ((const float4*)bl)[l * 32 + lane];
            acc.x += gate * (m.x + b.x);
            acc.y += gate * (m.y + b.y);
            acc.z += gate * (m.z + b.z);
            acc.w += gate * (m.w + b.w);
            e = en;
        }
    }

    acc.x = fmaxf(acc.x, 0.f); acc.y = fmaxf(acc.y, 0.f);
    acc.z = fmaxf(acc.z, 0.f); acc.w = fmaxf(acc.w, 0.f);
    ((float4*)out)[(size_t)v * 32 + lane] = acc;
}

// ---------------- launch ----------------
extern "C" void kernel_launch(void* const* d_in, const int* in_sizes, int n_in,
                              void* d_out, int out_size) {
    const float* x        = (const float*)d_in[0];
    const int* ei         = (const int*)d_in[1];   // [2, E] int32
    const int* lab        = (const int*)d_in[2];   // [E] int32
    const float* W_loop   = (const float*)d_in[3];
    const float* b_loop   = (const float*)d_in[4];
    const float* Wg_loop  = (const float*)d_in[5];
    const float* bg_loop  = (const float*)d_in[6];
    const float* W_in     = (const float*)d_in[7];
    const float* blab_in  = (const float*)d_in[8];
    const float* Wg_in    = (const float*)d_in[9];
    const float* bg_in    = (const float*)d_in[10];
    const float* W_out    = (const float*)d_in[11];
    const float* blab_out = (const float*)d_in[12];
    const float* Wg_out   = (const float*)d_in[13];
    const float* bg_out   = (const float*)d_in[14];

    int N = in_sizes[0] / DIMS;
    int E = in_sizes[2];

    // weights prep
    prep_w2_kernel<<<dim3(DIMS, 2), DIMS>>>(W_in, W_out);
    prep_c_kernel<<<1, 32>>>(Wg_in, blab_in, bg_in, Wg_out, blab_out, bg_out);
    prep_wt_kernel<<<3, 256>>>(W_loop);

    // CSR build
    zero_cnt_kernel<<<(N + 255) / 256, 256>>>(N);
    hist_kernel<<<(E + 255) / 256, 256>>>(ei, ei + E, E, N);
    scan_kernel<<<1, 1024>>>(N);
    fill_kernel<<<(E + 255) / 256, 256>>>(ei, ei + E, lab, E, N);

    // node GEMMs + fused epilogues
    cudaFuncSetAttribute(gemm_mma_kernel, cudaFuncAttributeMaxDynamicSharedMemorySize,
                         GEMM_SMEM);
    gemm_mma_kernel<<<(N + 127) / 128, GTHREADS, GEMM_SMEM>>>(
        x, b_loop, Wg_loop, bg_loop, Wg_in, Wg_out, N);

    // gather (replaces edge scatter + relu): warp per node
    gather_kernel<<<(N * 32 + 255) / 256, 256>>>(blab_in, blab_out, (float*)d_out, N);
}

// round 16
// speedup vs baseline: 1.8749x; 1.8749x over previous
#include <cuda_runtime.h>
#include <cuda_fp16.h>
#include <cstdint>

#define DIMS 128
#define NLAB 5
#define MAXN 50000
#define GTHREADS 512

// ---------------- device scratch ----------------
__device__ float g_W2[2][DIMS * DIMS];        // W_in@W_in, W_out@W_out (fp32)
__device__ float g_Wt[3][DIMS * 144];         // prepacked tf32 B^T images (quad layout)
__device__ float g_c[2][NLAB];                // per-label gate constants
__device__ float g_gate[2][MAXN];             // per-node h.Wg scalars (fp32)
__device__ __half g_hin[MAXN * DIMS];         // x @ (W_in @ W_in)   (fp16 storage)
__device__ __half g_hout[MAXN * DIMS];        // x @ (W_out @ W_out) (fp16 storage)
__device__ float g_acc[MAXN * DIMS];          // accumulator (xl + scatter sums, fp32)

__device__ __forceinline__ float sigmoidf_(float x) {
    return 1.0f / (1.0f + __expf(-x));
}

__device__ __forceinline__ float tf32r(float x) {
    uint32_t u;
    asm("cvt.rna.tf32.f32 %0, %1;" : "=r"(u) : "f"(x));
    return __uint_as_float(u);
}

__device__ __forceinline__ void mma_tf32(float* c, uint32_t a0, uint32_t a1,
                                         uint32_t a2, uint32_t a3,
                                         uint32_t b0, uint32_t b1) {
    asm volatile(
        "mma.sync.aligned.m16n8k8.row.col.f32.tf32.tf32.f32 "
        "{%0,%1,%2,%3}, {%4,%5,%6,%7}, {%8,%9}, {%0,%1,%2,%3};"
        : "+f"(c[0]), "+f"(c[1]), "+f"(c[2]), "+f"(c[3])
        : "r"(a0), "r"(a1), "r"(a2), "r"(a3), "r"(b0), "r"(b1));
}

__device__ __forceinline__ float4 h8_to_f4(uint2 raw) {
    float2 lo = __half22float2(*(__half2*)&raw.x);
    float2 hi = __half22float2(*(__half2*)&raw.y);
    return make_float4(lo.x, lo.y, hi.x, hi.y);
}

// ---------------- prep: W2 = W @ W ----------------
__global__ void prep_w2_kernel(const float* __restrict__ Win,
                               const float* __restrict__ Wout) {
    __shared__ float wrow[DIMS];
    const float* W = (blockIdx.y == 0) ? Win : Wout;
    int r = blockIdx.x, c = threadIdx.x;
    wrow[c] = W[r * DIMS + c];
    __syncthreads();
    float s = 0.0f;
#pragma unroll 8
    for (int k = 0; k < DIMS; k++) s += wrow[k] * W[k * DIMS + c];
    g_W2[blockIdx.y][r * DIMS + c] = s;
}

// ---------------- prep: gate constants ----------------
__global__ void prep_c_kernel(const float* __restrict__ Wg_in,
                              const float* __restrict__ blab_in,
                              const float* __restrict__ bg_in,
                              const float* __restrict__ Wg_out,
                              const float* __restrict__ blab_out,
                              const float* __restrict__ bg_out) {
    int t = threadIdx.x;
    if (t >= 2 * NLAB) return;
    int w = t / NLAB, l = t % NLAB;
    const float* Wg = w ? Wg_out : Wg_in;
    const float* bl = w ? blab_out : blab_in;
    const float* bg = w ? bg_out : bg_in;
    float s = bg[l];
    for (int d = 0; d < DIMS; d++) s += bl[l * DIMS + d] * Wg[d];
    g_c[w][l] = s;
}

// ---------------- prep: quad-layout tf32 W images ----------------
__global__ void prep_wt_kernel(const float* __restrict__ Wloop) {
    int w = blockIdx.x;
    const float* W = (w == 0) ? Wloop : g_W2[w - 1];
    for (int idx = threadIdx.x; idx < DIMS * DIMS; idx += blockDim.x) {
        int k = idx >> 7, n = idx & 127;
        float v = W[idx];
        int ks = k >> 3, kk = k & 7;
        int pos = (ks >> 1) * 16 + (kk & 3) * 4 + (ks & 1) * 2 + (kk >> 2);
        g_Wt[w][n * 144 + pos] = tf32r(v);
    }
}

// ---------------- mma.sync tf32 GEMM (R14 structure; h stored fp16) ----------------
#define AS_STRIDE 132
#define WH_STRIDE 144
#define SMEM_AS 0
#define SMEM_WH (128 * AS_STRIDE)
#define ST_STRIDE 132
#define GEMM_SMEM ((128 * AS_STRIDE + 128 * WH_STRIDE) * 4)

__global__ __launch_bounds__(GTHREADS) void gemm_mma_kernel(const float* __restrict__ x,
                                                            const float* __restrict__ b_loop,
                                                            const float* __restrict__ Wg_loop,
                                                            const float* __restrict__ bg_loop,
                                                            const float* __restrict__ Wg_in,
                                                            const float* __restrict__ Wg_out,
                                                            int M) {
    extern __shared__ float smem[];
    float* As = smem + SMEM_AS;
    float* Wh = smem + SMEM_WH;     // reused as store-staging buffer
    __shared__ float sg[DIMS * 2];

    int tid = threadIdx.x;
    int wid = tid >> 5, lane = tid & 31;
    int g = lane >> 2, t4 = lane & 3;
    int rg = wid & 7;
    int ch = wid >> 3;
    int m0 = blockIdx.x * 128;
    int m0w = rg * 16;

    const float4* x4 = (const float4*)x;
#pragma unroll
    for (int i = 0; i < 8; i++) {
        int fidx = tid + i * GTHREADS;
        int r = fidx >> 5, kq = fidx & 31;
        float4 v = make_float4(0.f, 0.f, 0.f, 0.f);
        if (m0 + r < M) v = x4[(size_t)(m0 + r) * 32 + kq];
        v.x = tf32r(v.x); v.y = tf32r(v.y); v.z = tf32r(v.z); v.w = tf32r(v.w);
        *(float4*)&As[r * AS_STRIDE + kq * 4] = v;
    }
    __syncthreads();

    int rloc0 = m0w + g, rloc1 = rloc0 + 8;
    const float* pa0 = As + rloc0 * AS_STRIDE;
    const float* pa1 = As + rloc1 * AS_STRIDE;
    uint32_t af[16][4];
#pragma unroll
    for (int ks = 0; ks < 16; ks++) {
        int k0 = ks * 8;
        af[ks][0] = __float_as_uint(pa0[k0 + t4]);
        af[ks][1] = __float_as_uint(pa1[k0 + t4]);
        af[ks][2] = __float_as_uint(pa0[k0 + t4 + 4]);
        af[ks][3] = __float_as_uint(pa1[k0 + t4 + 4]);
    }

    for (int w = 0; w < 3; w++) {
        __syncthreads();
        {
            const float4* srcp = (const float4*)g_Wt[w];
            float4* dstp = (float4*)Wh;
#pragma unroll
            for (int i = 0; i < 9; i++) {
                int fi = tid + i * GTHREADS;
                if (fi < 128 * WH_STRIDE / 4) dstp[fi] = srcp[fi];
            }
        }
        __syncthreads();

        float acc[8][4];
#pragma unroll
        for (int j = 0; j < 8; j++)
#pragma unroll
            for (int q = 0; q < 4; q++) acc[j][q] = 0.0f;

#pragma unroll
        for (int ks2 = 0; ks2 < 8; ks2++) {
            int ke = ks2 * 2, ko = ke + 1;
#pragma unroll
            for (int j = 0; j < 8; j++) {
                int n = (ch * 8 + j) * 8 + g;
                float4 bq = *(const float4*)&Wh[n * WH_STRIDE + ks2 * 16 + t4 * 4];
                mma_tf32(acc[j], af[ke][0], af[ke][1], af[ke][2], af[ke][3],
                         __float_as_uint(bq.x), __float_as_uint(bq.y));
                mma_tf32(acc[j], af[ko][0], af[ko][1], af[ko][2], af[ko][3],
                         __float_as_uint(bq.z), __float_as_uint(bq.w));
            }
        }

        float p0 = 0.f, p1 = 0.f;
        if (w == 0) {
#pragma unroll
            for (int j = 0; j < 8; j++) {
                int c0 = ch * 64 + j * 8 + t4 * 2;
                float2 bl2 = *(const float2*)&b_loop[c0];
                float2 wg2 = *(const float2*)&Wg_loop[c0];
                acc[j][0] += bl2.x; acc[j][1] += bl2.y;
                acc[j][2] += bl2.x; acc[j][3] += bl2.y;
                p0 += acc[j][0] * wg2.x + acc[j][1] * wg2.y;
                p1 += acc[j][2] * wg2.x + acc[j][3] * wg2.y;
            }
        } else {
            const float* Wg = (w == 2) ? Wg_out : Wg_in;
#pragma unroll
            for (int j = 0; j < 8; j++) {
                int c0 = ch * 64 + j * 8 + t4 * 2;
                float2 wg2 = *(const float2*)&Wg[c0];
                p0 += acc[j][0] * wg2.x + acc[j][1] * wg2.y;
                p1 += acc[j][2] * wg2.x + acc[j][3] * wg2.y;
            }
        }
        p0 += __shfl_xor_sync(0xffffffffu, p0, 1);
        p0 += __shfl_xor_sync(0xffffffffu, p0, 2);
        p1 += __shfl_xor_sync(0xffffffffu, p1, 1);
        p1 += __shfl_xor_sync(0xffffffffu, p1, 2);
        if (t4 == 0) {
            sg[rloc0 * 2 + ch] = p0;
            sg[rloc1 * 2 + ch] = p1;
        }
        __syncthreads();

        if (w == 0) {
            float bgv = __ldg(&bg_loop[0]);
            float g0 = sigmoidf_(sg[rloc0 * 2] + sg[rloc0 * 2 + 1] + bgv);
            float g1 = sigmoidf_(sg[rloc1 * 2] + sg[rloc1 * 2 + 1] + bgv);
#pragma unroll
            for (int j = 0; j < 8; j++) {
                acc[j][0] *= g0; acc[j][1] *= g0;
                acc[j][2] *= g1; acc[j][3] *= g1;
            }
        } else {
            int dir = w - 1;
            if (tid < DIMS) {
                int row = m0 + tid;
                if (row < M) g_gate[dir][row] = sg[tid * 2] + sg[tid * 2 + 1];
            }
        }

        float* stage = Wh;
#pragma unroll
        for (int j = 0; j < 8; j++) {
            int c0 = ch * 64 + j * 8 + t4 * 2;
            *(float2*)&stage[rloc0 * ST_STRIDE + c0] = make_float2(acc[j][0], acc[j][1]);
            *(float2*)&stage[rloc1 * ST_STRIDE + c0] = make_float2(acc[j][2], acc[j][3]);
        }
        __syncthreads();

        if (w == 0) {
#pragma unroll
            for (int i = 0; i < 8; i++) {
                int fidx = tid + i * GTHREADS;
                int r = fidx >> 5, cq = fidx & 31;
                int row = m0 + r;
                if (row < M)
                    *(float4*)&g_acc[(size_t)row * 128 + cq * 4] = *(float4*)&stage[r * ST_STRIDE + cq * 4];
            }
        } else {
            __half* outp = (w == 1) ? g_hin : g_hout;
#pragma unroll
            for (int i = 0; i < 8; i++) {
                int fidx = tid + i * GTHREADS;
                int r = fidx >> 5, cq = fidx & 31;
                int row = m0 + r;
                if (row < M) {
                    float4 v = *(float4*)&stage[r * ST_STRIDE + cq * 4];
                    __half2 h0 = __floats2half2_rn(v.x, v.y);
                    __half2 h1 = __floats2half2_rn(v.z, v.w);
                    uint2 u = make_uint2(*(uint32_t*)&h0, *(uint32_t*)&h1);
                    ((uint2*)outp)[(size_t)row * 32 + cq] = u;
                }
            }
        }
    }
}

// ---------------- fused edge scatter: 2 edges per warp, fp16 gathers, vec4 atomics ----------------
__global__ void edge_fused_kernel(const int* __restrict__ src,
                                  const int* __restrict__ dst,
                                  const int* __restrict__ lab,
                                  const float* __restrict__ blab_in,
                                  const float* __restrict__ blab_out,
                                  int E, int N) {
    int gw = (int)((blockIdx.x * (unsigned)blockDim.x + threadIdx.x) >> 5);
    int lane = threadIdx.x & 31;
    int e0 = gw * 2;
    if (e0 >= E) return;
    int e1 = e0 + 1;
    bool do1 = (e1 < E);
    if (!do1) e1 = e0;

    int s0 = min(max(src[e0], 0), N - 1), d0 = min(max(dst[e0], 0), N - 1);
    int l0 = min(max(lab[e0], 0), NLAB - 1);
    int s1 = min(max(src[e1], 0), N - 1), d1 = min(max(dst[e1], 0), N - 1);
    int l1 = min(max(lab[e1], 0), NLAB - 1);

    float gi0 = sigmoidf_(g_gate[0][s0] + g_c[0][l0]);
    float go0 = sigmoidf_(g_gate[1][d0] + g_c[1][l0]);
    float gi1 = sigmoidf_(g_gate[0][s1] + g_c[0][l1]);
    float go1 = sigmoidf_(g_gate[1][d1] + g_c[1][l1]);

    const uint2* hin2 = (const uint2*)g_hin;
    const uint2* hout2 = (const uint2*)g_hout;
    uint2 ri0 = hin2[(size_t)s0 * 32 + lane];
    uint2 ro0 = hout2[(size_t)d0 * 32 + lane];
    uint2 ri1 = hin2[(size_t)s1 * 32 + lane];
    uint2 ro1 = hout2[(size_t)d1 * 32 + lane];

    float4 bi0 = ((const float4*)blab_in)[l0 * 32 + lane];
    float4 bo0 = ((const float4*)blab_out)[l0 * 32 + lane];
    float4 bi1 = ((const float4*)blab_in)[l1 * 32 + lane];
    float4 bo1 = ((const float4*)blab_out)[l1 * 32 + lane];

    float4 mi0 = h8_to_f4(ri0);
    float4 mo0 = h8_to_f4(ro0);
    float4 vi0 = make_float4(gi0 * (mi0.x + bi0.x), gi0 * (mi0.y + bi0.y),
                             gi0 * (mi0.z + bi0.z), gi0 * (mi0.w + bi0.w));
    float4 vo0 = make_float4(go0 * (mo0.x + bo0.x), go0 * (mo0.y + bo0.y),
                             go0 * (mo0.z + bo0.z), go0 * (mo0.w + bo0.w));
    atomicAdd(((float4*)g_acc) + (size_t)d0 * 32 + lane, vi0);
    atomicAdd(((float4*)g_acc) + (size_t)s0 * 32 + lane, vo0);

    if (do1) {
        float4 mi1 = h8_to_f4(ri1);
        float4 mo1 = h8_to_f4(ro1);
        float4 vi1 = make_float4(gi1 * (mi1.x + bi1.x), gi1 * (mi1.y + bi1.y),
                                 gi1 * (mi1.z + bi1.z), gi1 * (mi1.w + bi1.w));
        float4 vo1 = make_float4(go1 * (mo1.x + bo1.x), go1 * (mo1.y + bo1.y),
                                 go1 * (mo1.z + bo1.z), go1 * (mo1.w + bo1.w));
        atomicAdd(((float4*)g_acc) + (size_t)d1 * 32 + lane, vi1);
        atomicAdd(((float4*)g_acc) + (size_t)s1 * 32 + lane, vo1);
    }
}

// ---------------- final relu: g_acc -> d_out ----------------
__global__ void relu_kernel(float* __restrict__ out, int n4) {
    int i = blockIdx.x * blockDim.x + threadIdx.x;
    if (i < n4) {
        float4 v = ((const float4*)g_acc)[i];
        v.x = fmaxf(v.x, 0.f); v.y = fmaxf(v.y, 0.f);
        v.z = fmaxf(v.z, 0.f); v.w = fmaxf(v.w, 0.f);
        ((float4*)out)[i] = v;
    }
}

// ---------------- launch ----------------
extern "C" void kernel_launch(void* const* d_in, const int* in_sizes, int n_in,
                              void* d_out, int out_size) {
    const float* x        = (const float*)d_in[0];
    const int* ei         = (const int*)d_in[1];   // [2, E] int32
    const int* lab        = (const int*)d_in[2];   // [E] int32
    const float* W_loop   = (const float*)d_in[3];
    const float* b_loop   = (const float*)d_in[4];
    const float* Wg_loop  = (const float*)d_in[5];
    const float* bg_loop  = (const float*)d_in[6];
    const float* W_in     = (const float*)d_in[7];
    const float* blab_in  = (const float*)d_in[8];
    const float* Wg_in    = (const float*)d_in[9];
    const float* bg_in    = (const float*)d_in[10];
    const float* W_out    = (const float*)d_in[11];
    const float* blab_out = (const float*)d_in[12];
    const float* Wg_out   = (const float*)d_in[13];
    const float* bg_out   = (const float*)d_in[14];

    int N = in_sizes[0] / DIMS;
    int E = in_sizes[2];

    prep_w2_kernel<<<dim3(DIMS, 2), DIMS>>>(W_in, W_out);
    prep_c_kernel<<<1, 32>>>(Wg_in, blab_in, bg_in, Wg_out, blab_out, bg_out);
    prep_wt_kernel<<<3, 256>>>(W_loop);

    cudaFuncSetAttribute(gemm_mma_kernel, cudaFuncAttributeMaxDynamicSharedMemorySize,
                         GEMM_SMEM);
    gemm_mma_kernel<<<(N + 127) / 128, GTHREADS, GEMM_SMEM>>>(
        x, b_loop, Wg_loop, bg_loop, Wg_in, Wg_out, N);

    int warps = (E + 1) / 2;
    int eblocks = (warps + 7) / 8;
    edge_fused_kernel<<<eblocks, 256>>>(ei, ei + E, lab, blab_in, blab_out, E, N);

    int n4 = N * DIMS / 4;
    relu_kernel<<<(n4 + 255) / 256, 256>>>((float*)d_out, n4);
}